// round 1
// baseline (speedup 1.0000x reference)
#include <cuda_runtime.h>

// DynamicRouting: N=64, C=4, H=W=256 fp32.
// out_x = mx0*conv1x1(x,e1) + my0*conv1x1(y,e3)   [64,4,256,256]
// out_y = mx1*conv1x1(x,e2) + my1*conv1x1(y,e4)   [64,8,256,256]
// gates from per-sample channel means through 2-layer tiny MLP, thresholded >0.

#define HW   65536
#define HW4  16384
#define NSMP 64

// scratch (allocation-free rule: __device__ globals)
__device__ float g_sums[512];          // [0..255]: x sums (n*4+c), [256..511]: y sums
__device__ float g_coef[NSMP * 112];   // per-sample folded coefficients

// ---------------------------------------------------------------------------
// Pass 1: per-(tensor, n, c) row sums. 512 blocks x 256 threads.
// Each row = 65536 contiguous floats = 16384 float4.
// ---------------------------------------------------------------------------
__global__ void sum_kernel(const float* __restrict__ x, const float* __restrict__ y) {
    int b = blockIdx.x;
    const float* base = (b < 256) ? (x + (size_t)b * HW)
                                  : (y + (size_t)(b - 256) * HW);
    const float4* src = (const float4*)base;

    float s0 = 0.f, s1 = 0.f, s2 = 0.f, s3 = 0.f;
    int t = threadIdx.x;
    // 16384 float4 / 256 threads = 64 per thread, 4-way unrolled (MLP=4)
    for (int i = t; i < HW4; i += 1024) {
        float4 v0 = src[i];
        float4 v1 = src[i + 256];
        float4 v2 = src[i + 512];
        float4 v3 = src[i + 768];
        s0 += v0.x + v0.y + v0.z + v0.w;
        s1 += v1.x + v1.y + v1.z + v1.w;
        s2 += v2.x + v2.y + v2.z + v2.w;
        s3 += v3.x + v3.y + v3.z + v3.w;
    }
    float s = (s0 + s1) + (s2 + s3);

    // warp reduce
    #pragma unroll
    for (int o = 16; o > 0; o >>= 1)
        s += __shfl_down_sync(0xffffffffu, s, o);

    __shared__ float ws[8];
    if ((t & 31) == 0) ws[t >> 5] = s;
    __syncthreads();
    if (t < 8) {
        s = ws[t];
        #pragma unroll
        for (int o = 4; o > 0; o >>= 1)
            s += __shfl_down_sync(0xffu, s, o);
        if (t == 0) g_sums[b] = s;
    }
}

// ---------------------------------------------------------------------------
// Gate kernel: 1 block, 64 threads (one per sample). Computes the tiny routing
// MLP for x and y, thresholds, and folds masks + biases into effective
// per-sample weights so the main pass is a plain dense op.
// Coef layout per sample (112 floats):
//   [  0.. 15]  Ax[o*4+c] = mx0 * w_e1[o][c]
//   [ 16.. 31]  Ay[o*4+c] = my0 * w_e3[o][c]
//   [ 32.. 35]  bx[o]     = mx0 * b_e1[o] + my0 * b_e3[o]
//   [ 36.. 67]  Bx[o*4+c] = mx1 * w_e2[o][c]
//   [ 68.. 99]  By[o*4+c] = my1 * w_e4[o][c]
//   [100..107]  by[o]     = mx1 * b_e2[o] + my1 * b_e4[o]
// ---------------------------------------------------------------------------
__global__ void gate_kernel(const float* __restrict__ w_rf1, const float* __restrict__ b_rf1,
                            const float* __restrict__ w_rf2, const float* __restrict__ b_rf2,
                            const float* __restrict__ w_e1,  const float* __restrict__ b_e1,
                            const float* __restrict__ w_e2,  const float* __restrict__ b_e2,
                            const float* __restrict__ w_e3,  const float* __restrict__ b_e3,
                            const float* __restrict__ w_e4,  const float* __restrict__ b_e4) {
    int n = threadIdx.x;
    if (n >= NSMP) return;
    const float inv = 1.0f / (float)HW;

    float px[4], py[4];
    #pragma unroll
    for (int c = 0; c < 4; c++) {
        px[c] = g_sums[n * 4 + c] * inv;
        py[c] = g_sums[256 + n * 4 + c] * inv;
    }

    // layer1: [2,4], layer2: [2,2]
    float gx1[2], gy1[2];
    #pragma unroll
    for (int j = 0; j < 2; j++) {
        float ax = b_rf1[j], ay = b_rf1[j];
        #pragma unroll
        for (int c = 0; c < 4; c++) {
            ax += px[c] * w_rf1[j * 4 + c];
            ay += py[c] * w_rf1[j * 4 + c];
        }
        gx1[j] = ax; gy1[j] = ay;
    }
    float gx[2], gy[2];
    #pragma unroll
    for (int i = 0; i < 2; i++) {
        float ax = b_rf2[i], ay = b_rf2[i];
        #pragma unroll
        for (int j = 0; j < 2; j++) {
            ax += gx1[j] * w_rf2[i * 2 + j];
            ay += gy1[j] * w_rf2[i * 2 + j];
        }
        gx[i] = ax; gy[i] = ay;
    }

    float mx0 = gx[0] > 0.f ? 1.f : 0.f;
    float mx1 = gx[1] > 0.f ? 1.f : 0.f;
    float my0 = gy[0] > 0.f ? 1.f : 0.f;
    float my1 = gy[1] > 0.f ? 1.f : 0.f;

    float* cf = g_coef + n * 112;
    #pragma unroll
    for (int i = 0; i < 16; i++) {
        cf[i]      = mx0 * w_e1[i];
        cf[16 + i] = my0 * w_e3[i];
    }
    #pragma unroll
    for (int o = 0; o < 4; o++)
        cf[32 + o] = mx0 * b_e1[o] + my0 * b_e3[o];
    #pragma unroll
    for (int i = 0; i < 32; i++) {
        cf[36 + i] = mx1 * w_e2[i];
        cf[68 + i] = my1 * w_e4[i];
    }
    #pragma unroll
    for (int o = 0; o < 8; o++)
        cf[100 + o] = mx1 * b_e2[o] + my1 * b_e4[o];
}

// ---------------------------------------------------------------------------
// Pass 2: fused dense elementwise pass. grid = (HW4/256, N).
// Each thread: 1 float4 position; loads 4 x-channels + 4 y-channels (float4),
// writes 4 out_x channels + 8 out_y channels (float4). Fully coalesced.
// ---------------------------------------------------------------------------
__global__ void __launch_bounds__(256)
main_kernel(const float* __restrict__ x, const float* __restrict__ y,
            float* __restrict__ out) {
    __shared__ float cf[112];
    int n = blockIdx.y;
    if (threadIdx.x < 112) cf[threadIdx.x] = g_coef[n * 112 + threadIdx.x];
    __syncthreads();

    int pid = blockIdx.x * 256 + threadIdx.x;   // float4 index within plane

    const float4* xb = (const float4*)(x + (size_t)n * 4 * HW);
    const float4* yb = (const float4*)(y + (size_t)n * 4 * HW);

    float4 xv[4], yv[4];
    #pragma unroll
    for (int c = 0; c < 4; c++) {
        xv[c] = xb[(size_t)c * HW4 + pid];
        yv[c] = yb[(size_t)c * HW4 + pid];
    }

    // out_x: 4 channels
    float4* ox = (float4*)(out + (size_t)n * 4 * HW);
    #pragma unroll
    for (int o = 0; o < 4; o++) {
        float b = cf[32 + o];
        float4 acc = make_float4(b, b, b, b);
        #pragma unroll
        for (int c = 0; c < 4; c++) {
            float a1 = cf[o * 4 + c];
            float a2 = cf[16 + o * 4 + c];
            acc.x += a1 * xv[c].x + a2 * yv[c].x;
            acc.y += a1 * xv[c].y + a2 * yv[c].y;
            acc.z += a1 * xv[c].z + a2 * yv[c].z;
            acc.w += a1 * xv[c].w + a2 * yv[c].w;
        }
        ox[(size_t)o * HW4 + pid] = acc;
    }

    // out_y: 8 channels, located after out_x block
    float4* oy = (float4*)(out + (size_t)NSMP * 4 * HW + (size_t)n * 8 * HW);
    #pragma unroll
    for (int o = 0; o < 8; o++) {
        float b = cf[100 + o];
        float4 acc = make_float4(b, b, b, b);
        #pragma unroll
        for (int c = 0; c < 4; c++) {
            float a1 = cf[36 + o * 4 + c];
            float a2 = cf[68 + o * 4 + c];
            acc.x += a1 * xv[c].x + a2 * yv[c].x;
            acc.y += a1 * xv[c].y + a2 * yv[c].y;
            acc.z += a1 * xv[c].z + a2 * yv[c].z;
            acc.w += a1 * xv[c].w + a2 * yv[c].w;
        }
        oy[(size_t)o * HW4 + pid] = acc;
    }
}

// ---------------------------------------------------------------------------
extern "C" void kernel_launch(void* const* d_in, const int* in_sizes, int n_in,
                              void* d_out, int out_size) {
    const float* x = (const float*)d_in[0];
    const float* y = (const float*)d_in[1];

    sum_kernel<<<512, 256>>>(x, y);

    gate_kernel<<<1, 64>>>((const float*)d_in[2],  (const float*)d_in[3],
                           (const float*)d_in[4],  (const float*)d_in[5],
                           (const float*)d_in[6],  (const float*)d_in[7],
                           (const float*)d_in[8],  (const float*)d_in[9],
                           (const float*)d_in[10], (const float*)d_in[11],
                           (const float*)d_in[12], (const float*)d_in[13]);

    dim3 grid(HW4 / 256, NSMP);
    main_kernel<<<grid, 256>>>(x, y, (float*)d_out);
}